// round 14
// baseline (speedup 1.0000x reference)
#include <cuda_runtime.h>
#include <cstdint>

#define E_ACT 4
#define T_TOK 4096
#define D_DIM 1024
#define H_DIM 5632
#define CAP   4096
#define BK    16

// ---------------- scratch (static device globals; no allocation) ----------------
__device__ int   g_counts[E_ACT];
__device__ int   g_tok[E_ACT * CAP];
__device__ float g_wgt[E_ACT * CAP];
__device__ int   g_rows[T_TOK * 2];
__device__ float g_h[(size_t)E_ACT * CAP * H_DIM];   // SwiGLU activations
__device__ float g_y[(size_t)E_ACT * CAP * D_DIM];   // per-(token,expert) scaled outputs

// ---------------- helpers ----------------
__device__ __forceinline__ uint32_t f2tf(float f) {
    uint32_t r;
    asm("cvt.rna.tf32.f32 %0, %1;" : "=r"(r) : "f"(f));
    return r;
}

__device__ __forceinline__ void mma_tf32(float c[4], const uint32_t a[4], const uint32_t b[2]) {
    asm volatile(
        "mma.sync.aligned.m16n8k8.row.col.f32.tf32.tf32.f32 "
        "{%0,%1,%2,%3}, {%4,%5,%6,%7}, {%8,%9}, {%0,%1,%2,%3};\n"
        : "+f"(c[0]), "+f"(c[1]), "+f"(c[2]), "+f"(c[3])
        : "r"(a[0]), "r"(a[1]), "r"(a[2]), "r"(a[3]), "r"(b[0]), "r"(b[1]));
}

__device__ __forceinline__ void cp_async16(void* smem, const void* gmem) {
    uint32_t s = (uint32_t)__cvta_generic_to_shared(smem);
    asm volatile("cp.async.cg.shared.global [%0], [%1], 16;\n" :: "r"(s), "l"(gmem));
}
__device__ __forceinline__ void cp_commit() { asm volatile("cp.async.commit_group;\n"); }
template <int N>
__device__ __forceinline__ void cp_wait() { asm volatile("cp.async.wait_group %0;\n" :: "n"(N)); }

// ---------------- kernel 0: reset routing counters ----------------
__global__ void zero_counts_kernel() {
    if (threadIdx.x < E_ACT) g_counts[threadIdx.x] = 0;
}

// ---------------- kernel 1: gate + route (1 warp per token) ----------------
__global__ __launch_bounds__(256) void gate_kernel(const float* __restrict__ x,
                                                   const float* __restrict__ gate_w) {
    __shared__ float gws[E_ACT][D_DIM];
    int tid = threadIdx.x;
    for (int i = tid * 4; i < E_ACT * D_DIM; i += 256 * 4) {
        *(float4*)&gws[0][i] = *(const float4*)&gate_w[i];   // rows 0..3 only
    }
    __syncthreads();

    int warp = tid >> 5, lane = tid & 31;
    int t = blockIdx.x * 8 + warp;
    const float* xp = x + (size_t)t * D_DIM;

    float a0 = 0.f, a1 = 0.f, a2 = 0.f, a3 = 0.f;
    for (int i = lane; i < D_DIM; i += 32) {
        float xv = xp[i];
        a0 += xv * gws[0][i];
        a1 += xv * gws[1][i];
        a2 += xv * gws[2][i];
        a3 += xv * gws[3][i];
    }
#pragma unroll
    for (int off = 16; off; off >>= 1) {
        a0 += __shfl_xor_sync(0xffffffffu, a0, off);
        a1 += __shfl_xor_sync(0xffffffffu, a1, off);
        a2 += __shfl_xor_sync(0xffffffffu, a2, off);
        a3 += __shfl_xor_sync(0xffffffffu, a3, off);
    }

    if (lane == 0) {
        float l[4] = {a0, a1, a2, a3};
        int b0 = 0;
#pragma unroll
        for (int e2 = 1; e2 < 4; e2++) if (l[e2] > l[b0]) b0 = e2;   // stable argmax
        int b1 = (b0 == 0) ? 1 : 0;
#pragma unroll
        for (int e2 = 0; e2 < 4; e2++) if (e2 != b0 && l[e2] > l[b1]) b1 = e2;

        float wa = 1.0f / (1.0f + expf(l[b1] - l[b0]));  // renormalized top-2 softmax
        float wb = 1.0f - wa;

        int p0 = atomicAdd(&g_counts[b0], 1);
        g_tok[b0 * CAP + p0] = t;
        g_wgt[b0 * CAP + p0] = wa;
        g_rows[t * 2 + 0] = b0 * CAP + p0;

        int p1 = atomicAdd(&g_counts[b1], 1);
        g_tok[b1 * CAP + p1] = t;
        g_wgt[b1 * CAP + p1] = wb;
        g_rows[t * 2 + 1] = b1 * CAP + p1;
    }
}

// ---------------- kernel 2: grouped GEMM  h = silu(X@W1) * (X@W3) ----------------
// grid (H/64, CAP/64, E_ACT), 128 threads (4 warps 2x2), CTA tile 64x64,
// warp tile 32x32 per matrix (R6 structure). 4 CTAs/SM -> independent barrier
// domains so LDS-phase of one CTA overlaps MMA-phase of another.
struct P1Smem {
    float Xs[3][64][20];    // pad 4: a-load banks 20g+tg -> conflict-free
    float W1[3][BK][72];    // 72 = 8 mod 32: b-load banks 8tg+g -> conflict-free
    float W3[3][BK][72];
    int   toks[64];
};

__global__ __launch_bounds__(128, 4) void pass1_kernel(const float* __restrict__ x,
                                                       const float* __restrict__ w1,
                                                       const float* __restrict__ w3) {
    extern __shared__ char smem_raw[];
    P1Smem* sm = (P1Smem*)smem_raw;

    int e = blockIdx.z;
    int Ne = g_counts[e];
    int m0 = blockIdx.y * 64;
    if (m0 >= Ne) return;
    int n0 = blockIdx.x * 64;

    int tid = threadIdx.x;
    if (tid < 64) {
        int r = m0 + tid;
        sm->toks[tid] = g_tok[e * CAP + (r < Ne ? r : 0)];
    }
    __syncthreads();

    // loader geometry: X = 64 rows x 16 floats (2 float4/thread)
    int xrow = tid >> 1;              // 0..63
    int xc = (tid & 1) * 8;           // 0 or 8; chunks at xc, xc+4
    const float* xg = x + (size_t)sm->toks[xrow] * D_DIM + xc;
    // W = 16 rows x 64 floats (2 float4/thread each tensor)
    int wr = tid >> 3;                // 0..15
    int wc = (tid & 7) * 8;           // 0..56; chunks at wc, wc+4
    const float* w1g = w1 + ((size_t)e * D_DIM + wr) * H_DIM + n0 + wc;
    const float* w3g = w3 + ((size_t)e * D_DIM + wr) * H_DIM + n0 + wc;

    auto load_stage = [&](int s) {
        int buf = s % 3;
        int k0 = s * BK;
        cp_async16(&sm->Xs[buf][xrow][xc],     xg + k0);
        cp_async16(&sm->Xs[buf][xrow][xc + 4], xg + k0 + 4);
        size_t woff = (size_t)k0 * H_DIM;
        cp_async16(&sm->W1[buf][wr][wc],     w1g + woff);
        cp_async16(&sm->W1[buf][wr][wc + 4], w1g + woff + 4);
        cp_async16(&sm->W3[buf][wr][wc],     w3g + woff);
        cp_async16(&sm->W3[buf][wr][wc + 4], w3g + woff + 4);
        cp_commit();
    };

    int warp = tid >> 5, lane = tid & 31;
    int wm = warp >> 1, wn = warp & 1;        // 2x2 warps: 32x32 per warp per matrix
    int g = lane >> 2, tg = lane & 3;

    float c1[2][4][4], c3[2][4][4];
#pragma unroll
    for (int mi = 0; mi < 2; mi++)
#pragma unroll
        for (int ni = 0; ni < 4; ni++)
#pragma unroll
            for (int r = 0; r < 4; r++) { c1[mi][ni][r] = 0.f; c3[mi][ni][r] = 0.f; }

    // double-buffered register fragments
    uint32_t a[2][2][4], b1f[2][4][2], b3f[2][4][2];
    auto loadfrag = [&](int s, int buf, int k8) {
#pragma unroll
        for (int mi = 0; mi < 2; mi++) {
            int rb = wm * 32 + mi * 16;
            a[s][mi][0] = f2tf(sm->Xs[buf][rb + g][k8 + tg]);
            a[s][mi][1] = f2tf(sm->Xs[buf][rb + g + 8][k8 + tg]);
            a[s][mi][2] = f2tf(sm->Xs[buf][rb + g][k8 + tg + 4]);
            a[s][mi][3] = f2tf(sm->Xs[buf][rb + g + 8][k8 + tg + 4]);
        }
#pragma unroll
        for (int ni = 0; ni < 4; ni++) {
            int col = wn * 32 + ni * 8 + g;
            b1f[s][ni][0] = f2tf(sm->W1[buf][k8 + tg][col]);
            b1f[s][ni][1] = f2tf(sm->W1[buf][k8 + tg + 4][col]);
            b3f[s][ni][0] = f2tf(sm->W3[buf][k8 + tg][col]);
            b3f[s][ni][1] = f2tf(sm->W3[buf][k8 + tg + 4][col]);
        }
    };

    const int NK = D_DIM / BK;   // 64
    load_stage(0);
    load_stage(1);

    for (int i = 0; i < NK; i++) {
        cp_wait<1>();            // stage i landed (1 commit per iteration invariant)
        __syncthreads();
        if (i + 2 < NK) load_stage(i + 2);
        else cp_commit();        // empty group keeps wait<1> tail-correct

        int buf = i % 3;
        loadfrag(0, buf, 0);
#pragma unroll
        for (int kk = 0; kk < BK / 8; kk++) {
            int cur = kk & 1;
            if (kk + 1 < BK / 8) loadfrag(cur ^ 1, buf, (kk + 1) * 8);
#pragma unroll
            for (int ni = 0; ni < 4; ni++)
#pragma unroll
                for (int mi = 0; mi < 2; mi++) {
                    mma_tf32(c1[mi][ni], a[cur][mi], b1f[cur][ni]);
                    mma_tf32(c3[mi][ni], a[cur][mi], b3f[cur][ni]);
                }
        }
    }

    // epilogue: SwiGLU, write fp32 h
#pragma unroll
    for (int mi = 0; mi < 2; mi++) {
#pragma unroll
        for (int hi = 0; hi < 2; hi++) {
            int row = m0 + wm * 32 + mi * 16 + g + hi * 8;
            if (row < Ne) {
                size_t base = ((size_t)e * CAP + row) * H_DIM + n0 + wn * 32;
#pragma unroll
                for (int ni = 0; ni < 4; ni++) {
                    float v1a = c1[mi][ni][hi * 2 + 0], v1b = c1[mi][ni][hi * 2 + 1];
                    float v3a = c3[mi][ni][hi * 2 + 0], v3b = c3[mi][ni][hi * 2 + 1];
                    float2 hv;
                    hv.x = (v1a / (1.f + expf(-v1a))) * v3a;
                    hv.y = (v1b / (1.f + expf(-v1b))) * v3b;
                    *(float2*)&g_h[base + ni * 8 + 2 * tg] = hv;
                }
            }
        }
    }
}

// ---------------- kernel 3: grouped GEMM  y = (h @ W2) * gate_weight ----------------
// grid (D/128, CAP/64, E_ACT), 128 threads (4 warps 2x2), CTA tile 64x128,
// warp tile 32x64 (R6 structure). 4 CTAs/SM.
struct P2Smem {
    float Hs[3][64][20];
    float Ws[3][BK][136];   // 136 = 8 mod 32 -> conflict-free b loads
};

__global__ __launch_bounds__(128, 4) void pass2_kernel(const float* __restrict__ w2) {
    extern __shared__ char smem_raw[];
    P2Smem* sm = (P2Smem*)smem_raw;

    int e = blockIdx.z;
    int Ne = g_counts[e];
    int m0 = blockIdx.y * 64;
    if (m0 >= Ne) return;
    int n0 = blockIdx.x * 128;

    int tid = threadIdx.x;
    int warp = tid >> 5, lane = tid & 31;
    int wm = warp >> 1, wn = warp & 1;        // 2x2 warps: warp tile 32x64
    int g = lane >> 2, tg = lane & 3;

    int xrow = tid >> 1;
    int xc = (tid & 1) * 8;
    const float* hg = g_h + ((size_t)e * CAP + m0 + xrow) * H_DIM + xc;
    int wr = tid >> 3;                 // 0..15
    int wc = (tid & 7) * 16;           // 0..112; chunks at wc, +4, +8, +12
    const float* wg = w2 + ((size_t)e * H_DIM + wr) * D_DIM + n0 + wc;

    auto load_stage = [&](int s) {
        int buf = s % 3;
        int k0 = s * BK;
        cp_async16(&sm->Hs[buf][xrow][xc],     hg + k0);
        cp_async16(&sm->Hs[buf][xrow][xc + 4], hg + k0 + 4);
        size_t woff = (size_t)k0 * D_DIM;
        cp_async16(&sm->Ws[buf][wr][wc],      wg + woff);
        cp_async16(&sm->Ws[buf][wr][wc + 4],  wg + woff + 4);
        cp_async16(&sm->Ws[buf][wr][wc + 8],  wg + woff + 8);
        cp_async16(&sm->Ws[buf][wr][wc + 12], wg + woff + 12);
        cp_commit();
    };

    float cc[2][8][4];
#pragma unroll
    for (int mi = 0; mi < 2; mi++)
#pragma unroll
        for (int ni = 0; ni < 8; ni++)
#pragma unroll
            for (int r = 0; r < 4; r++) cc[mi][ni][r] = 0.f;

    uint32_t a[2][2][4], bf[2][8][2];
    auto loadfrag = [&](int s, int buf, int k8) {
#pragma unroll
        for (int mi = 0; mi < 2; mi++) {
            int rb = wm * 32 + mi * 16;
            a[s][mi][0] = f2tf(sm->Hs[buf][rb + g][k8 + tg]);
            a[s][mi][1] = f2tf(sm->Hs[buf][rb + g + 8][k8 + tg]);
            a[s][mi][2] = f2tf(sm->Hs[buf][rb + g][k8 + tg + 4]);
            a[s][mi][3] = f2tf(sm->Hs[buf][rb + g + 8][k8 + tg + 4]);
        }
#pragma unroll
        for (int ni = 0; ni < 8; ni++) {
            int col = wn * 64 + ni * 8 + g;
            bf[s][ni][0] = f2tf(sm->Ws[buf][k8 + tg][col]);
            bf[s][ni][1] = f2tf(sm->Ws[buf][k8 + tg + 4][col]);
        }
    };

    const int NK = H_DIM / BK;   // 352
    load_stage(0);
    load_stage(1);

    for (int i = 0; i < NK; i++) {
        cp_wait<1>();
        __syncthreads();
        if (i + 2 < NK) load_stage(i + 2);
        else cp_commit();

        int buf = i % 3;
        loadfrag(0, buf, 0);
#pragma unroll
        for (int kk = 0; kk < BK / 8; kk++) {
            int cur = kk & 1;
            if (kk + 1 < BK / 8) loadfrag(cur ^ 1, buf, (kk + 1) * 8);
#pragma unroll
            for (int ni = 0; ni < 8; ni++)
#pragma unroll
                for (int mi = 0; mi < 2; mi++)
                    mma_tf32(cc[mi][ni], a[cur][mi], bf[cur][ni]);
        }
    }

#pragma unroll
    for (int mi = 0; mi < 2; mi++) {
#pragma unroll
        for (int hi = 0; hi < 2; hi++) {
            int row = m0 + wm * 32 + mi * 16 + g + hi * 8;
            if (row < Ne) {
                float wrow = g_wgt[e * CAP + row];
                size_t base = ((size_t)e * CAP + row) * D_DIM + n0 + wn * 64;
#pragma unroll
                for (int ni = 0; ni < 8; ni++) {
                    float2 v;
                    v.x = cc[mi][ni][hi * 2 + 0] * wrow;
                    v.y = cc[mi][ni][hi * 2 + 1] * wrow;
                    *(float2*)&g_y[base + ni * 8 + 2 * tg] = v;
                }
            }
        }
    }
}

// ---------------- kernel 4: deterministic combine  out[t] = y[rowA] + y[rowB] ----------------
__global__ void combine_kernel(float* __restrict__ out) {
    int idx = blockIdx.x * blockDim.x + threadIdx.x;   // float4 index, T*D/4 total
    int t = idx >> 8;                                  // 256 float4 per token row
    int c = (idx & 255) * 4;
    int rA = g_rows[t * 2 + 0];
    int rB = g_rows[t * 2 + 1];
    float4 a = *(const float4*)&g_y[(size_t)rA * D_DIM + c];
    float4 b = *(const float4*)&g_y[(size_t)rB * D_DIM + c];
    float4 o;
    o.x = a.x + b.x; o.y = a.y + b.y; o.z = a.z + b.z; o.w = a.w + b.w;
    *(float4*)&out[(size_t)t * D_DIM + c] = o;
}

// ---------------- launch ----------------
extern "C" void kernel_launch(void* const* d_in, const int* in_sizes, int n_in,
                              void* d_out, int out_size) {
    const float* x      = (const float*)d_in[0];
    const float* gate_w = (const float*)d_in[1];
    const float* w1     = (const float*)d_in[2];
    const float* w2     = (const float*)d_in[3];
    const float* w3     = (const float*)d_in[4];
    float* out = (float*)d_out;

    cudaFuncSetAttribute(pass1_kernel, cudaFuncAttributeMaxDynamicSharedMemorySize,
                         (int)sizeof(P1Smem));
    cudaFuncSetAttribute(pass2_kernel, cudaFuncAttributeMaxDynamicSharedMemorySize,
                         (int)sizeof(P2Smem));

    zero_counts_kernel<<<1, 32>>>();
    gate_kernel<<<T_TOK / 8, 256>>>(x, gate_w);
    pass1_kernel<<<dim3(H_DIM / 64, CAP / 64, E_ACT), 128, sizeof(P1Smem)>>>(x, w1, w3);
    pass2_kernel<<<dim3(D_DIM / 128, CAP / 64, E_ACT), 128, sizeof(P2Smem)>>>(w2);
    combine_kernel<<<(T_TOK * D_DIM / 4) / 256, 256>>>(out);
}

// round 15
// speedup vs baseline: 1.1867x; 1.1867x over previous
#include <cuda_runtime.h>
#include <cstdint>

#define E_ACT 4
#define T_TOK 4096
#define D_DIM 1024
#define H_DIM 5632
#define CAP   4096
#define BK    32
#define NGRID 296          // 2 CTAs/SM x 148 SMs: persistent worker count

// ---------------- scratch (static device globals; no allocation) ----------------
__device__ int   g_counts[E_ACT];
__device__ int   g_tok[E_ACT * CAP];
__device__ float g_wgt[E_ACT * CAP];
__device__ int   g_rows[T_TOK * 2];
__device__ int   g_mpre[E_ACT + 1];   // prefix of ceil(Ne/128) per expert
__device__ int   g_tick[2];           // tile tickets for pass1 / pass2
__device__ float g_h[(size_t)E_ACT * CAP * H_DIM];   // SwiGLU activations
__device__ float g_y[(size_t)E_ACT * CAP * D_DIM];   // per-(token,expert) scaled outputs

// ---------------- helpers ----------------
__device__ __forceinline__ uint32_t f2tf(float f) {
    uint32_t r;
    asm("cvt.rna.tf32.f32 %0, %1;" : "=r"(r) : "f"(f));
    return r;
}

__device__ __forceinline__ void mma_tf32(float c[4], const uint32_t a[4], const uint32_t b[2]) {
    asm volatile(
        "mma.sync.aligned.m16n8k8.row.col.f32.tf32.tf32.f32 "
        "{%0,%1,%2,%3}, {%4,%5,%6,%7}, {%8,%9}, {%0,%1,%2,%3};\n"
        : "+f"(c[0]), "+f"(c[1]), "+f"(c[2]), "+f"(c[3])
        : "r"(a[0]), "r"(a[1]), "r"(a[2]), "r"(a[3]), "r"(b[0]), "r"(b[1]));
}

__device__ __forceinline__ void cp_async16(void* smem, const void* gmem) {
    uint32_t s = (uint32_t)__cvta_generic_to_shared(smem);
    asm volatile("cp.async.cg.shared.global [%0], [%1], 16;\n" :: "r"(s), "l"(gmem));
}
__device__ __forceinline__ void cp_commit() { asm volatile("cp.async.commit_group;\n"); }
template <int N>
__device__ __forceinline__ void cp_wait() { asm volatile("cp.async.wait_group %0;\n" :: "n"(N)); }

// decode expert from global m-tile index via 4-entry prefix
__device__ __forceinline__ int find_e(int mt, const int* mp) {
    int e = 0;
    e += (mt >= mp[1]);
    e += (mt >= mp[2]);
    e += (mt >= mp[3]);
    return e;
}

// ---------------- kernel 0: reset routing counters ----------------
__global__ void zero_counts_kernel() {
    if (threadIdx.x < E_ACT) g_counts[threadIdx.x] = 0;
}

// ---------------- kernel 1: gate + route (1 warp per token) ----------------
__global__ __launch_bounds__(256) void gate_kernel(const float* __restrict__ x,
                                                   const float* __restrict__ gate_w) {
    __shared__ float gws[E_ACT][D_DIM];
    int tid = threadIdx.x;
    for (int i = tid * 4; i < E_ACT * D_DIM; i += 256 * 4) {
        *(float4*)&gws[0][i] = *(const float4*)&gate_w[i];   // rows 0..3 only
    }
    __syncthreads();

    int warp = tid >> 5, lane = tid & 31;
    int t = blockIdx.x * 8 + warp;
    const float* xp = x + (size_t)t * D_DIM;

    float a0 = 0.f, a1 = 0.f, a2 = 0.f, a3 = 0.f;
    for (int i = lane; i < D_DIM; i += 32) {
        float xv = xp[i];
        a0 += xv * gws[0][i];
        a1 += xv * gws[1][i];
        a2 += xv * gws[2][i];
        a3 += xv * gws[3][i];
    }
#pragma unroll
    for (int off = 16; off; off >>= 1) {
        a0 += __shfl_xor_sync(0xffffffffu, a0, off);
        a1 += __shfl_xor_sync(0xffffffffu, a1, off);
        a2 += __shfl_xor_sync(0xffffffffu, a2, off);
        a3 += __shfl_xor_sync(0xffffffffu, a3, off);
    }

    if (lane == 0) {
        float l[4] = {a0, a1, a2, a3};
        int b0 = 0;
#pragma unroll
        for (int e2 = 1; e2 < 4; e2++) if (l[e2] > l[b0]) b0 = e2;   // stable argmax
        int b1 = (b0 == 0) ? 1 : 0;
#pragma unroll
        for (int e2 = 0; e2 < 4; e2++) if (e2 != b0 && l[e2] > l[b1]) b1 = e2;

        float wa = 1.0f / (1.0f + expf(l[b1] - l[b0]));  // renormalized top-2 softmax
        float wb = 1.0f - wa;

        int p0 = atomicAdd(&g_counts[b0], 1);
        g_tok[b0 * CAP + p0] = t;
        g_wgt[b0 * CAP + p0] = wa;
        g_rows[t * 2 + 0] = b0 * CAP + p0;

        int p1 = atomicAdd(&g_counts[b1], 1);
        g_tok[b1 * CAP + p1] = t;
        g_wgt[b1 * CAP + p1] = wb;
        g_rows[t * 2 + 1] = b1 * CAP + p1;
    }
}

// ---------------- kernel 1b: tile plan (prefix of m-blocks, reset tickets) ----------------
__global__ void plan_kernel() {
    if (threadIdx.x == 0) {
        int p = 0;
#pragma unroll
        for (int e = 0; e < E_ACT; e++) {
            g_mpre[e] = p;
            p += (g_counts[e] + 127) / 128;
        }
        g_mpre[E_ACT] = p;
        g_tick[0] = 0;
        g_tick[1] = 0;
    }
}

// ---------------- kernel 2: grouped GEMM  h = silu(X@W1) * (X@W3) ----------------
// persistent CTAs (NGRID), 256 threads; tiles = (e, mb, nb) with nb over H/64.
// Body identical to R12: BK=32 3-stage cp.async pipeline + frag double-buffer.
struct P1Smem {
    float Xs[3][128][36];   // stride 36: a-load banks 4g+tg -> conflict-free
    float W1[3][BK][72];    // 72 = 8 mod 32: b-load banks 8tg+g -> conflict-free
    float W3[3][BK][72];
    int   toks[128];
    int   ticket;
};

__global__ __launch_bounds__(256, 2) void pass1_kernel(const float* __restrict__ x,
                                                       const float* __restrict__ w1,
                                                       const float* __restrict__ w3) {
    extern __shared__ char smem_raw[];
    P1Smem* sm = (P1Smem*)smem_raw;

    int tid = threadIdx.x;
    int warp = tid >> 5, lane = tid & 31;
    int wm = warp >> 1, wn = warp & 1;        // 4x2 warp grid: 32x32 per warp per matrix
    int g = lane >> 2, tg = lane & 3;

    int mp[E_ACT + 1];
#pragma unroll
    for (int e = 0; e <= E_ACT; e++) mp[e] = g_mpre[e];
    const int total = mp[E_ACT] * 88;

    for (;;) {
        if (tid == 0) sm->ticket = atomicAdd(&g_tick[0], 1);
        __syncthreads();                      // broadcast ticket + protect smem reuse
        int t = sm->ticket;
        if (t >= total) break;

        int mt = t / 88, nb = t % 88;         // nb fastest: consecutive tickets share X tile
        int e = find_e(mt, mp);
        int Ne = g_counts[e];
        int m0 = (mt - mp[e]) * 128;
        int n0 = nb * 64;

        if (tid < 128) {
            int r = m0 + tid;
            sm->toks[tid] = g_tok[e * CAP + (r < Ne ? r : 0)];
        }
        __syncthreads();

        int xrow = tid >> 2;
        int xc4 = (tid & 3) * 4;
        const float* xg0 = x + (size_t)sm->toks[xrow] * D_DIM + xc4;
        const float* xg1 = x + (size_t)sm->toks[xrow + 64] * D_DIM + xc4;
        int wr = tid >> 4;
        int wc = (tid & 15) * 4;
        const float* w1g = w1 + ((size_t)e * D_DIM + wr) * H_DIM + n0 + wc;
        const float* w3g = w3 + ((size_t)e * D_DIM + wr) * H_DIM + n0 + wc;

        auto load_stage = [&](int s) {
            int buf = s % 3;
            int k0 = s * BK;
            cp_async16(&sm->Xs[buf][xrow][xc4],           xg0 + k0);
            cp_async16(&sm->Xs[buf][xrow][xc4 + 16],      xg0 + k0 + 16);
            cp_async16(&sm->Xs[buf][xrow + 64][xc4],      xg1 + k0);
            cp_async16(&sm->Xs[buf][xrow + 64][xc4 + 16], xg1 + k0 + 16);
#pragma unroll
            for (int i = 0; i < 2; i++) {
                int kr = wr + 16 * i;
                size_t off = (size_t)(k0 + 16 * i) * H_DIM;
                cp_async16(&sm->W1[buf][kr][wc], w1g + off);
                cp_async16(&sm->W3[buf][kr][wc], w3g + off);
            }
            cp_commit();
        };

        float c1[2][4][4], c3[2][4][4];
#pragma unroll
        for (int mi = 0; mi < 2; mi++)
#pragma unroll
            for (int ni = 0; ni < 4; ni++)
#pragma unroll
                for (int r = 0; r < 4; r++) { c1[mi][ni][r] = 0.f; c3[mi][ni][r] = 0.f; }

        uint32_t a[2][2][4], b1f[2][4][2], b3f[2][4][2];
        auto loadfrag = [&](int s, int buf, int k8) {
#pragma unroll
            for (int mi = 0; mi < 2; mi++) {
                int rb = wm * 32 + mi * 16;
                a[s][mi][0] = f2tf(sm->Xs[buf][rb + g][k8 + tg]);
                a[s][mi][1] = f2tf(sm->Xs[buf][rb + g + 8][k8 + tg]);
                a[s][mi][2] = f2tf(sm->Xs[buf][rb + g][k8 + tg + 4]);
                a[s][mi][3] = f2tf(sm->Xs[buf][rb + g + 8][k8 + tg + 4]);
            }
#pragma unroll
            for (int ni = 0; ni < 4; ni++) {
                int col = wn * 32 + ni * 8 + g;
                b1f[s][ni][0] = f2tf(sm->W1[buf][k8 + tg][col]);
                b1f[s][ni][1] = f2tf(sm->W1[buf][k8 + tg + 4][col]);
                b3f[s][ni][0] = f2tf(sm->W3[buf][k8 + tg][col]);
                b3f[s][ni][1] = f2tf(sm->W3[buf][k8 + tg + 4][col]);
            }
        };

        const int NK = D_DIM / BK;   // 32
        load_stage(0);
        load_stage(1);

        for (int i = 0; i < NK; i++) {
            cp_wait<1>();            // stage i landed (1 commit per iteration invariant)
            __syncthreads();
            if (i + 2 < NK) load_stage(i + 2);
            else cp_commit();        // empty group keeps wait<1> tail-correct

            int buf = i % 3;
            loadfrag(0, buf, 0);
#pragma unroll
            for (int kk = 0; kk < BK / 8; kk++) {
                int cur = kk & 1;
                if (kk + 1 < BK / 8) loadfrag(cur ^ 1, buf, (kk + 1) * 8);
#pragma unroll
                for (int ni = 0; ni < 4; ni++)
#pragma unroll
                    for (int mi = 0; mi < 2; mi++) {
                        mma_tf32(c1[mi][ni], a[cur][mi], b1f[cur][ni]);
                        mma_tf32(c3[mi][ni], a[cur][mi], b3f[cur][ni]);
                    }
            }
        }

        // epilogue: SwiGLU, write fp32 h
#pragma unroll
        for (int mi = 0; mi < 2; mi++) {
#pragma unroll
            for (int hi = 0; hi < 2; hi++) {
                int row = m0 + wm * 32 + mi * 16 + g + hi * 8;
                if (row < Ne) {
                    size_t base = ((size_t)e * CAP + row) * H_DIM + n0 + wn * 32;
#pragma unroll
                    for (int ni = 0; ni < 4; ni++) {
                        float v1a = c1[mi][ni][hi * 2 + 0], v1b = c1[mi][ni][hi * 2 + 1];
                        float v3a = c3[mi][ni][hi * 2 + 0], v3b = c3[mi][ni][hi * 2 + 1];
                        float2 hv;
                        hv.x = (v1a / (1.f + expf(-v1a))) * v3a;
                        hv.y = (v1b / (1.f + expf(-v1b))) * v3b;
                        *(float2*)&g_h[base + ni * 8 + 2 * tg] = hv;
                    }
                }
            }
        }
    }
}

// ---------------- kernel 3: grouped GEMM  y = (h @ W2) * gate_weight ----------------
// persistent CTAs (NGRID), 256 threads; tiles = (e, mb, nb) with nb over D/128.
struct P2Smem {
    float Hs[3][128][36];
    float Ws[3][BK][136];   // 136 = 8 mod 32 -> conflict-free b loads
    int   ticket;
};

__global__ __launch_bounds__(256, 2) void pass2_kernel(const float* __restrict__ w2) {
    extern __shared__ char smem_raw[];
    P2Smem* sm = (P2Smem*)smem_raw;

    int tid = threadIdx.x;
    int warp = tid >> 5, lane = tid & 31;
    int wm = warp >> 1, wn = warp & 1;        // warp tile 32x64
    int g = lane >> 2, tg = lane & 3;

    int mp[E_ACT + 1];
#pragma unroll
    for (int e = 0; e <= E_ACT; e++) mp[e] = g_mpre[e];
    const int total = mp[E_ACT] * 8;

    for (;;) {
        if (tid == 0) sm->ticket = atomicAdd(&g_tick[1], 1);
        __syncthreads();
        int t = sm->ticket;
        if (t >= total) break;

        int mt = t >> 3, nb = t & 7;          // nb fastest: consecutive tickets share H tile
        int e = find_e(mt, mp);
        int Ne = g_counts[e];
        int m0 = (mt - mp[e]) * 128;
        int n0 = nb * 128;

        int xrow = tid >> 2;
        int xc4 = (tid & 3) * 4;
        const float* hg0 = g_h + ((size_t)e * CAP + m0 + xrow) * H_DIM + xc4;
        const float* hg1 = g_h + ((size_t)e * CAP + m0 + xrow + 64) * H_DIM + xc4;
        int wr = tid >> 5;
        int wc = (tid & 31) * 4;
        const float* wg = w2 + ((size_t)e * H_DIM + wr) * D_DIM + n0 + wc;

        auto load_stage = [&](int s) {
            int buf = s % 3;
            int k0 = s * BK;
            cp_async16(&sm->Hs[buf][xrow][xc4],           hg0 + k0);
            cp_async16(&sm->Hs[buf][xrow][xc4 + 16],      hg0 + k0 + 16);
            cp_async16(&sm->Hs[buf][xrow + 64][xc4],      hg1 + k0);
            cp_async16(&sm->Hs[buf][xrow + 64][xc4 + 16], hg1 + k0 + 16);
#pragma unroll
            for (int i = 0; i < 4; i++) {
                int kr = wr + 8 * i;
                cp_async16(&sm->Ws[buf][kr][wc], wg + (size_t)(k0 + 8 * i) * D_DIM);
            }
            cp_commit();
        };

        float cc[2][8][4];
#pragma unroll
        for (int mi = 0; mi < 2; mi++)
#pragma unroll
            for (int ni = 0; ni < 8; ni++)
#pragma unroll
                for (int r = 0; r < 4; r++) cc[mi][ni][r] = 0.f;

        uint32_t a[2][2][4], bf[2][8][2];
        auto loadfrag = [&](int s, int buf, int k8) {
#pragma unroll
            for (int mi = 0; mi < 2; mi++) {
                int rb = wm * 32 + mi * 16;
                a[s][mi][0] = f2tf(sm->Hs[buf][rb + g][k8 + tg]);
                a[s][mi][1] = f2tf(sm->Hs[buf][rb + g + 8][k8 + tg]);
                a[s][mi][2] = f2tf(sm->Hs[buf][rb + g][k8 + tg + 4]);
                a[s][mi][3] = f2tf(sm->Hs[buf][rb + g + 8][k8 + tg + 4]);
            }
#pragma unroll
            for (int ni = 0; ni < 8; ni++) {
                int col = wn * 64 + ni * 8 + g;
                bf[s][ni][0] = f2tf(sm->Ws[buf][k8 + tg][col]);
                bf[s][ni][1] = f2tf(sm->Ws[buf][k8 + tg + 4][col]);
            }
        };

        const int NK = H_DIM / BK;   // 176
        load_stage(0);
        load_stage(1);

        for (int i = 0; i < NK; i++) {
            cp_wait<1>();
            __syncthreads();
            if (i + 2 < NK) load_stage(i + 2);
            else cp_commit();

            int buf = i % 3;
            loadfrag(0, buf, 0);
#pragma unroll
            for (int kk = 0; kk < BK / 8; kk++) {
                int cur = kk & 1;
                if (kk + 1 < BK / 8) loadfrag(cur ^ 1, buf, (kk + 1) * 8);
#pragma unroll
                for (int ni = 0; ni < 8; ni++)
#pragma unroll
                    for (int mi = 0; mi < 2; mi++)
                        mma_tf32(cc[mi][ni], a[cur][mi], bf[cur][ni]);
            }
        }

#pragma unroll
        for (int mi = 0; mi < 2; mi++) {
#pragma unroll
            for (int hi = 0; hi < 2; hi++) {
                int row = m0 + wm * 32 + mi * 16 + g + hi * 8;
                if (row < Ne) {
                    float wrow = g_wgt[e * CAP + row];
                    size_t base = ((size_t)e * CAP + row) * D_DIM + n0 + wn * 64;
#pragma unroll
                    for (int ni = 0; ni < 8; ni++) {
                        float2 v;
                        v.x = cc[mi][ni][hi * 2 + 0] * wrow;
                        v.y = cc[mi][ni][hi * 2 + 1] * wrow;
                        *(float2*)&g_y[base + ni * 8 + 2 * tg] = v;
                    }
                }
            }
        }
    }
}

// ---------------- kernel 4: deterministic combine  out[t] = y[rowA] + y[rowB] ----------------
__global__ void combine_kernel(float* __restrict__ out) {
    int idx = blockIdx.x * blockDim.x + threadIdx.x;   // float4 index, T*D/4 total
    int t = idx >> 8;                                  // 256 float4 per token row
    int c = (idx & 255) * 4;
    int rA = g_rows[t * 2 + 0];
    int rB = g_rows[t * 2 + 1];
    float4 a = *(const float4*)&g_y[(size_t)rA * D_DIM + c];
    float4 b = *(const float4*)&g_y[(size_t)rB * D_DIM + c];
    float4 o;
    o.x = a.x + b.x; o.y = a.y + b.y; o.z = a.z + b.z; o.w = a.w + b.w;
    *(float4*)&out[(size_t)t * D_DIM + c] = o;
}

// ---------------- launch ----------------
extern "C" void kernel_launch(void* const* d_in, const int* in_sizes, int n_in,
                              void* d_out, int out_size) {
    const float* x      = (const float*)d_in[0];
    const float* gate_w = (const float*)d_in[1];
    const float* w1     = (const float*)d_in[2];
    const float* w2     = (const float*)d_in[3];
    const float* w3     = (const float*)d_in[4];
    float* out = (float*)d_out;

    cudaFuncSetAttribute(pass1_kernel, cudaFuncAttributeMaxDynamicSharedMemorySize,
                         (int)sizeof(P1Smem));
    cudaFuncSetAttribute(pass2_kernel, cudaFuncAttributeMaxDynamicSharedMemorySize,
                         (int)sizeof(P2Smem));

    zero_counts_kernel<<<1, 32>>>();
    gate_kernel<<<T_TOK / 8, 256>>>(x, gate_w);
    plan_kernel<<<1, 32>>>();
    pass1_kernel<<<NGRID, 256, sizeof(P1Smem)>>>(x, w1, w3);
    pass2_kernel<<<NGRID, 256, sizeof(P2Smem)>>>(w2);
    combine_kernel<<<(T_TOK * D_DIM / 4) / 256, 256>>>(out);
}

// round 16
// speedup vs baseline: 1.9777x; 1.6666x over previous
#include <cuda_runtime.h>
#include <cuda_fp16.h>
#include <cstdint>

#define E_ACT 4
#define T_TOK 4096
#define D_DIM 1024
#define H_DIM 5632
#define CAP   4096
#define BKH   32            // k halves per smem stage = 2 x k16 bodies

// ---------------- scratch (static device globals; no allocation) ----------------
__device__ int    g_counts[E_ACT];
__device__ int    g_tok[E_ACT * CAP];
__device__ float  g_wgt[E_ACT * CAP];
__device__ int    g_rows[T_TOK * 2];
__device__ __half g_xh[(size_t)T_TOK * D_DIM];            // fp16 x
__device__ __half g_w1h[(size_t)E_ACT * H_DIM * D_DIM];   // w1^T: [e][H][D] fp16
__device__ __half g_w3h[(size_t)E_ACT * H_DIM * D_DIM];   // w3^T: [e][H][D] fp16
__device__ __half g_w2h[(size_t)E_ACT * D_DIM * H_DIM];   // w2^T: [e][D][H] fp16
__device__ __half g_hh[(size_t)E_ACT * CAP * H_DIM];      // SwiGLU activations fp16
__device__ float  g_y[(size_t)E_ACT * CAP * D_DIM];       // scaled outputs fp32

// ---------------- helpers ----------------
__device__ __forceinline__ void mma_f16(float c[4], const uint32_t a[4], const uint32_t b[2]) {
    asm volatile(
        "mma.sync.aligned.m16n8k16.row.col.f32.f16.f16.f32 "
        "{%0,%1,%2,%3}, {%4,%5,%6,%7}, {%8,%9}, {%0,%1,%2,%3};\n"
        : "+f"(c[0]), "+f"(c[1]), "+f"(c[2]), "+f"(c[3])
        : "r"(a[0]), "r"(a[1]), "r"(a[2]), "r"(a[3]), "r"(b[0]), "r"(b[1]));
}

__device__ __forceinline__ void cp_async16(void* smem, const void* gmem) {
    uint32_t s = (uint32_t)__cvta_generic_to_shared(smem);
    asm volatile("cp.async.cg.shared.global [%0], [%1], 16;\n" :: "r"(s), "l"(gmem));
}
__device__ __forceinline__ void cp_commit() { asm volatile("cp.async.commit_group;\n"); }
template <int N>
__device__ __forceinline__ void cp_wait() { asm volatile("cp.async.wait_group %0;\n" :: "n"(N)); }

#define U32AT(p) (*(const uint32_t*)&(p))

// ---------------- kernel 0: reset routing counters ----------------
__global__ void zero_counts_kernel() {
    if (threadIdx.x < E_ACT) g_counts[threadIdx.x] = 0;
}

// ---------------- prep: x -> fp16 ----------------
__global__ __launch_bounds__(256) void cvt_half_kernel(__half* __restrict__ dst,
                                                       const float* __restrict__ src, int n4) {
    int i = blockIdx.x * blockDim.x + threadIdx.x;
    if (i < n4) {
        float4 v = *(const float4*)(src + (size_t)i * 4);
        *(__half2*)(dst + (size_t)i * 4)     = __floats2half2_rn(v.x, v.y);
        *(__half2*)(dst + (size_t)i * 4 + 2) = __floats2half2_rn(v.z, v.w);
    }
}

// ---------------- prep: transpose + fp16  src [R][C] -> dst [C][R], per expert ----------------
__global__ __launch_bounds__(256) void transpose_cvt_half(__half* __restrict__ dst,
                                                          const float* __restrict__ src,
                                                          int R, int C) {
    __shared__ float tile[32][33];
    size_t off = (size_t)blockIdx.z * R * C;
    int c0 = blockIdx.x * 32, r0 = blockIdx.y * 32;
    int tx = threadIdx.x & 31, ty = threadIdx.x >> 5;
#pragma unroll
    for (int j = ty; j < 32; j += 8)
        tile[j][tx] = src[off + (size_t)(r0 + j) * C + c0 + tx];
    __syncthreads();
#pragma unroll
    for (int j = ty; j < 32; j += 8)
        dst[off + (size_t)(c0 + j) * R + r0 + tx] = __float2half(tile[tx][j]);
}

// ---------------- kernel 1: gate + route (1 warp per token, fp32) ----------------
__global__ __launch_bounds__(256) void gate_kernel(const float* __restrict__ x,
                                                   const float* __restrict__ gate_w) {
    __shared__ float gws[E_ACT][D_DIM];
    int tid = threadIdx.x;
    for (int i = tid * 4; i < E_ACT * D_DIM; i += 256 * 4) {
        *(float4*)&gws[0][i] = *(const float4*)&gate_w[i];   // rows 0..3 only
    }
    __syncthreads();

    int warp = tid >> 5, lane = tid & 31;
    int t = blockIdx.x * 8 + warp;
    const float* xp = x + (size_t)t * D_DIM;

    float a0 = 0.f, a1 = 0.f, a2 = 0.f, a3 = 0.f;
    for (int i = lane; i < D_DIM; i += 32) {
        float xv = xp[i];
        a0 += xv * gws[0][i];
        a1 += xv * gws[1][i];
        a2 += xv * gws[2][i];
        a3 += xv * gws[3][i];
    }
#pragma unroll
    for (int off = 16; off; off >>= 1) {
        a0 += __shfl_xor_sync(0xffffffffu, a0, off);
        a1 += __shfl_xor_sync(0xffffffffu, a1, off);
        a2 += __shfl_xor_sync(0xffffffffu, a2, off);
        a3 += __shfl_xor_sync(0xffffffffu, a3, off);
    }

    if (lane == 0) {
        float l[4] = {a0, a1, a2, a3};
        int b0 = 0;
#pragma unroll
        for (int e2 = 1; e2 < 4; e2++) if (l[e2] > l[b0]) b0 = e2;   // stable argmax
        int b1 = (b0 == 0) ? 1 : 0;
#pragma unroll
        for (int e2 = 0; e2 < 4; e2++) if (e2 != b0 && l[e2] > l[b1]) b1 = e2;

        float wa = 1.0f / (1.0f + expf(l[b1] - l[b0]));  // renormalized top-2 softmax
        float wb = 1.0f - wa;

        int p0 = atomicAdd(&g_counts[b0], 1);
        g_tok[b0 * CAP + p0] = t;
        g_wgt[b0 * CAP + p0] = wa;
        g_rows[t * 2 + 0] = b0 * CAP + p0;

        int p1 = atomicAdd(&g_counts[b1], 1);
        g_tok[b1 * CAP + p1] = t;
        g_wgt[b1 * CAP + p1] = wb;
        g_rows[t * 2 + 1] = b1 * CAP + p1;
    }
}

// ---------------- kernel 2: grouped GEMM  h = silu(X@W1) * (X@W3)  [fp16 mma] ----------------
// grid (H/64, CAP/128, E_ACT), 256 threads, 4x2 warps (32x32 per warp per matrix).
// A [128][BKH] and B tiles [64 n][BKH k] fp16, padded to 40 halves/row:
// word index = 20*row + tg (mod 32) is a perfect bank permutation for fragment loads.
struct P1Smem {
    __half Xs[3][128][40];
    __half W1[3][64][40];
    __half W3[3][64][40];
    int    toks[128];
};

__global__ __launch_bounds__(256, 2) void pass1_kernel() {
    extern __shared__ char smem_raw[];
    P1Smem* sm = (P1Smem*)smem_raw;

    int e = blockIdx.z;
    int Ne = g_counts[e];
    int m0 = blockIdx.y * 128;
    if (m0 >= Ne) return;
    int n0 = blockIdx.x * 64;

    int tid = threadIdx.x;
    if (tid < 128) {
        int r = m0 + tid;
        sm->toks[tid] = g_tok[e * CAP + (r < Ne ? r : 0)];
    }
    __syncthreads();

    // loaders: A 128x32 halves (2 cp16/thread), W 64x32 halves (1 cp16/thread each)
    int xrow = tid >> 1;
    int xcb = (tid & 1) * 16;
    const __half* xg = g_xh + (size_t)sm->toks[xrow] * D_DIM + xcb;
    int wrow = tid >> 2;              // 0..63
    int wch = (tid & 3) * 8;
    const __half* w1g = g_w1h + ((size_t)e * H_DIM + n0 + wrow) * D_DIM + wch;
    const __half* w3g = g_w3h + ((size_t)e * H_DIM + n0 + wrow) * D_DIM + wch;

    auto load_stage = [&](int s) {
        int buf = s % 3;
        int k0 = s * BKH;
        cp_async16(&sm->Xs[buf][xrow][xcb],     xg + k0);
        cp_async16(&sm->Xs[buf][xrow][xcb + 8], xg + k0 + 8);
        cp_async16(&sm->W1[buf][wrow][wch], w1g + k0);
        cp_async16(&sm->W3[buf][wrow][wch], w3g + k0);
        cp_commit();
    };

    int warp = tid >> 5, lane = tid & 31;
    int wm = warp >> 1, wn = warp & 1;
    int g = lane >> 2, tg = lane & 3;

    float c1[2][4][4], c3[2][4][4];
#pragma unroll
    for (int mi = 0; mi < 2; mi++)
#pragma unroll
        for (int ni = 0; ni < 4; ni++)
#pragma unroll
            for (int r = 0; r < 4; r++) { c1[mi][ni][r] = 0.f; c3[mi][ni][r] = 0.f; }

    uint32_t a[2][2][4], b1f[2][4][2], b3f[2][4][2];
    auto loadfrag = [&](int s, int buf, int k16) {
#pragma unroll
        for (int mi = 0; mi < 2; mi++) {
            int rb = wm * 32 + mi * 16;
            a[s][mi][0] = U32AT(sm->Xs[buf][rb + g][k16 + 2 * tg]);
            a[s][mi][1] = U32AT(sm->Xs[buf][rb + g + 8][k16 + 2 * tg]);
            a[s][mi][2] = U32AT(sm->Xs[buf][rb + g][k16 + 2 * tg + 8]);
            a[s][mi][3] = U32AT(sm->Xs[buf][rb + g + 8][k16 + 2 * tg + 8]);
        }
#pragma unroll
        for (int ni = 0; ni < 4; ni++) {
            int col = wn * 32 + ni * 8 + g;
            b1f[s][ni][0] = U32AT(sm->W1[buf][col][k16 + 2 * tg]);
            b1f[s][ni][1] = U32AT(sm->W1[buf][col][k16 + 2 * tg + 8]);
            b3f[s][ni][0] = U32AT(sm->W3[buf][col][k16 + 2 * tg]);
            b3f[s][ni][1] = U32AT(sm->W3[buf][col][k16 + 2 * tg + 8]);
        }
    };

    const int NK = D_DIM / BKH;   // 32
    load_stage(0);
    load_stage(1);

    for (int i = 0; i < NK; i++) {
        cp_wait<1>();            // stage i landed (1 commit per iteration invariant)
        __syncthreads();
        if (i + 2 < NK) load_stage(i + 2);
        else cp_commit();        // empty group keeps wait<1> tail-correct

        int buf = i % 3;
        loadfrag(0, buf, 0);
#pragma unroll
        for (int kk = 0; kk < BKH / 16; kk++) {
            int cur = kk & 1;
            if (kk + 1 < BKH / 16) loadfrag(cur ^ 1, buf, (kk + 1) * 16);
#pragma unroll
            for (int ni = 0; ni < 4; ni++)
#pragma unroll
                for (int mi = 0; mi < 2; mi++) {
                    mma_f16(c1[mi][ni], a[cur][mi], b1f[cur][ni]);
                    mma_f16(c3[mi][ni], a[cur][mi], b3f[cur][ni]);
                }
        }
    }

    // epilogue: SwiGLU in fp32, store fp16 h (c0,c1 = cols 2tg,2tg+1 -> __half2)
#pragma unroll
    for (int mi = 0; mi < 2; mi++) {
#pragma unroll
        for (int hi = 0; hi < 2; hi++) {
            int row = m0 + wm * 32 + mi * 16 + g + hi * 8;
            if (row < Ne) {
                size_t base = ((size_t)e * CAP + row) * H_DIM + n0 + wn * 32;
#pragma unroll
                for (int ni = 0; ni < 4; ni++) {
                    float v1a = c1[mi][ni][hi * 2 + 0], v1b = c1[mi][ni][hi * 2 + 1];
                    float v3a = c3[mi][ni][hi * 2 + 0], v3b = c3[mi][ni][hi * 2 + 1];
                    float s0 = (v1a / (1.f + expf(-v1a))) * v3a;
                    float s1 = (v1b / (1.f + expf(-v1b))) * v3b;
                    *(__half2*)&g_hh[base + ni * 8 + 2 * tg] = __floats2half2_rn(s0, s1);
                }
            }
        }
    }
}

// ---------------- kernel 3: grouped GEMM  y = (h @ W2) * gate_weight  [fp16 mma] ----------------
// grid (D/128, CAP/128, E_ACT), 256 threads, warp tile 32x64.
struct P2Smem {
    __half Hs[3][128][40];
    __half Ws[3][128][40];
};

__global__ __launch_bounds__(256, 2) void pass2_kernel() {
    extern __shared__ char smem_raw[];
    P2Smem* sm = (P2Smem*)smem_raw;

    int e = blockIdx.z;
    int Ne = g_counts[e];
    int m0 = blockIdx.y * 128;
    if (m0 >= Ne) return;
    int n0 = blockIdx.x * 128;

    int tid = threadIdx.x;
    int warp = tid >> 5, lane = tid & 31;
    int wm = warp >> 1, wn = warp & 1;
    int g = lane >> 2, tg = lane & 3;

    int xrow = tid >> 1;
    int xcb = (tid & 1) * 16;
    const __half* hg = g_hh + ((size_t)e * CAP + m0 + xrow) * H_DIM + xcb;
    const __half* wg = g_w2h + ((size_t)e * D_DIM + n0 + xrow) * H_DIM + xcb;

    auto load_stage = [&](int s) {
        int buf = s % 3;
        int k0 = s * BKH;
        cp_async16(&sm->Hs[buf][xrow][xcb],     hg + k0);
        cp_async16(&sm->Hs[buf][xrow][xcb + 8], hg + k0 + 8);
        cp_async16(&sm->Ws[buf][xrow][xcb],     wg + k0);
        cp_async16(&sm->Ws[buf][xrow][xcb + 8], wg + k0 + 8);
        cp_commit();
    };

    float cc[2][8][4];
#pragma unroll
    for (int mi = 0; mi < 2; mi++)
#pragma unroll
        for (int ni = 0; ni < 8; ni++)
#pragma unroll
            for (int r = 0; r < 4; r++) cc[mi][ni][r] = 0.f;

    uint32_t a[2][2][4], bf[2][8][2];
    auto loadfrag = [&](int s, int buf, int k16) {
#pragma unroll
        for (int mi = 0; mi < 2; mi++) {
            int rb = wm * 32 + mi * 16;
            a[s][mi][0] = U32AT(sm->Hs[buf][rb + g][k16 + 2 * tg]);
            a[s][mi][1] = U32AT(sm->Hs[buf][rb + g + 8][k16 + 2 * tg]);
            a[s][mi][2] = U32AT(sm->Hs[buf][rb + g][k16 + 2 * tg + 8]);
            a[s][mi][3] = U32AT(sm->Hs[buf][rb + g + 8][k16 + 2 * tg + 8]);
        }
#pragma unroll
        for (int ni = 0; ni < 8; ni++) {
            int col = wn * 64 + ni * 8 + g;
            bf[s][ni][0] = U32AT(sm->Ws[buf][col][k16 + 2 * tg]);
            bf[s][ni][1] = U32AT(sm->Ws[buf][col][k16 + 2 * tg + 8]);
        }
    };

    const int NK = H_DIM / BKH;   // 176
    load_stage(0);
    load_stage(1);

    for (int i = 0; i < NK; i++) {
        cp_wait<1>();
        __syncthreads();
        if (i + 2 < NK) load_stage(i + 2);
        else cp_commit();

        int buf = i % 3;
        loadfrag(0, buf, 0);
#pragma unroll
        for (int kk = 0; kk < BKH / 16; kk++) {
            int cur = kk & 1;
            if (kk + 1 < BKH / 16) loadfrag(cur ^ 1, buf, (kk + 1) * 16);
#pragma unroll
            for (int ni = 0; ni < 8; ni++)
#pragma unroll
                for (int mi = 0; mi < 2; mi++)
                    mma_f16(cc[mi][ni], a[cur][mi], bf[cur][ni]);
        }
    }

#pragma unroll
    for (int mi = 0; mi < 2; mi++) {
#pragma unroll
        for (int hi = 0; hi < 2; hi++) {
            int row = m0 + wm * 32 + mi * 16 + g + hi * 8;
            if (row < Ne) {
                float wrow = g_wgt[e * CAP + row];
                size_t base = ((size_t)e * CAP + row) * D_DIM + n0 + wn * 64;
#pragma unroll
                for (int ni = 0; ni < 8; ni++) {
                    float2 v;
                    v.x = cc[mi][ni][hi * 2 + 0] * wrow;
                    v.y = cc[mi][ni][hi * 2 + 1] * wrow;
                    *(float2*)&g_y[base + ni * 8 + 2 * tg] = v;
                }
            }
        }
    }
}

// ---------------- kernel 4: deterministic combine  out[t] = y[rowA] + y[rowB] ----------------
__global__ void combine_kernel(float* __restrict__ out) {
    int idx = blockIdx.x * blockDim.x + threadIdx.x;   // float4 index, T*D/4 total
    int t = idx >> 8;                                  // 256 float4 per token row
    int c = (idx & 255) * 4;
    int rA = g_rows[t * 2 + 0];
    int rB = g_rows[t * 2 + 1];
    float4 a = *(const float4*)&g_y[(size_t)rA * D_DIM + c];
    float4 b = *(const float4*)&g_y[(size_t)rB * D_DIM + c];
    float4 o;
    o.x = a.x + b.x; o.y = a.y + b.y; o.z = a.z + b.z; o.w = a.w + b.w;
    *(float4*)&out[(size_t)t * D_DIM + c] = o;
}

// ---------------- launch ----------------
extern "C" void kernel_launch(void* const* d_in, const int* in_sizes, int n_in,
                              void* d_out, int out_size) {
    const float* x      = (const float*)d_in[0];
    const float* gate_w = (const float*)d_in[1];
    const float* w1     = (const float*)d_in[2];
    const float* w2     = (const float*)d_in[3];
    const float* w3     = (const float*)d_in[4];
    float* out = (float*)d_out;

    cudaFuncSetAttribute(pass1_kernel, cudaFuncAttributeMaxDynamicSharedMemorySize,
                         (int)sizeof(P1Smem));
    cudaFuncSetAttribute(pass2_kernel, cudaFuncAttributeMaxDynamicSharedMemorySize,
                         (int)sizeof(P2Smem));

    __half *xh, *w1h, *w3h, *w2h;
    cudaGetSymbolAddress((void**)&xh,  g_xh);
    cudaGetSymbolAddress((void**)&w1h, g_w1h);
    cudaGetSymbolAddress((void**)&w3h, g_w3h);
    cudaGetSymbolAddress((void**)&w2h, g_w2h);

    zero_counts_kernel<<<1, 32>>>();
    gate_kernel<<<T_TOK / 8, 256>>>(x, gate_w);
    // prep: fp16 conversions (+ weight transposes to [n][k]); experts 0..3 only
    cvt_half_kernel<<<(T_TOK * D_DIM / 4 + 255) / 256, 256>>>(xh, x, T_TOK * D_DIM / 4);
    transpose_cvt_half<<<dim3(H_DIM / 32, D_DIM / 32, E_ACT), 256>>>(w1h, w1, D_DIM, H_DIM);
    transpose_cvt_half<<<dim3(H_DIM / 32, D_DIM / 32, E_ACT), 256>>>(w3h, w3, D_DIM, H_DIM);
    transpose_cvt_half<<<dim3(D_DIM / 32, H_DIM / 32, E_ACT), 256>>>(w2h, w2, H_DIM, D_DIM);

    pass1_kernel<<<dim3(H_DIM / 64, CAP / 128, E_ACT), 256, sizeof(P1Smem)>>>();
    pass2_kernel<<<dim3(D_DIM / 128, CAP / 128, E_ACT), 256, sizeof(P2Smem)>>>();
    combine_kernel<<<(T_TOK * D_DIM / 4) / 256, 256>>>(out);
}